// round 9
// baseline (speedup 1.0000x reference)
#include <cuda_runtime.h>
#include <cuda_bf16.h>
#include <math.h>
#include <stdint.h>

// Problem constants
#define BATCH   64
#define NTOK    236
#define CDIM    768
#define HEADS   8
#define HDIM    96
#define C3      2304
#define S1C     196
#define S2C     216
#define BIASV   100.0f
#define MROWS   (BATCH * NTOK)   // 15104

// Scratch (device globals; no allocation allowed)
__device__ float g_qkv[(size_t)MROWS * C3];   // [15104, 2304] fp32
__device__ float g_att[(size_t)MROWS * CDIM]; // [15104, 768]  tf32-rounded
__device__ float g_xc [(size_t)MROWS * CDIM]; // x, tf32-rounded
__device__ float g_wqc[(size_t)C3 * CDIM];    // qkv_w, tf32-rounded
__device__ float g_wpc[(size_t)CDIM * CDIM];  // proj_w, tf32-rounded

__device__ __forceinline__ unsigned f2tf(unsigned x) {
    unsigned y;
    asm volatile("cvt.rna.tf32.f32 %0, %1;\n" : "=r"(y) : "r"(x));
    return y;
}
__device__ __forceinline__ float f2tf_f(float x) {
    return __uint_as_float(f2tf(__float_as_uint(x)));
}

// ---------------------------------------------------------------------------
// Elementwise fp32 -> tf32(rna) pre-conversion (vectorized)
// ---------------------------------------------------------------------------
__global__ __launch_bounds__(256) void cvt_tf32_kernel(
    const float* __restrict__ in, float* __restrict__ out, int n4)
{
    int i = blockIdx.x * blockDim.x + threadIdx.x;
    if (i < n4) {
        float4 v = ((const float4*)in)[i];
        v.x = f2tf_f(v.x); v.y = f2tf_f(v.y);
        v.z = f2tf_f(v.z); v.w = f2tf_f(v.w);
        ((float4*)out)[i] = v;
    }
}

// ---------------------------------------------------------------------------
// MMA / staging helpers
// ---------------------------------------------------------------------------
__device__ __forceinline__ void ldsm4(unsigned* r, unsigned addr) {
    asm volatile("ldmatrix.sync.aligned.m8n8.x4.shared.b16 {%0,%1,%2,%3}, [%4];\n"
        : "=r"(r[0]), "=r"(r[1]), "=r"(r[2]), "=r"(r[3]) : "r"(addr));
}
__device__ __forceinline__ void mma_tf32(float* c, const unsigned* a,
                                         unsigned b0, unsigned b1) {
    asm volatile(
        "mma.sync.aligned.m16n8k8.row.col.f32.tf32.tf32.f32 "
        "{%0,%1,%2,%3}, {%4,%5,%6,%7}, {%8,%9}, {%0,%1,%2,%3};\n"
        : "+f"(c[0]), "+f"(c[1]), "+f"(c[2]), "+f"(c[3])
        : "r"(a[0]), "r"(a[1]), "r"(a[2]), "r"(a[3]), "r"(b0), "r"(b1));
}
__device__ __forceinline__ void cp16(unsigned dst, const void* src) {
    asm volatile("cp.async.cg.shared.global [%0], [%1], 16;\n" :: "r"(dst), "l"(src));
}
__device__ __forceinline__ void cp_commit() {
    asm volatile("cp.async.commit_group;\n" ::);
}
__device__ __forceinline__ void cp_wait1() {
    asm volatile("cp.async.wait_group 1;\n" ::);
}
__device__ __forceinline__ unsigned swz(int row, int c) {
    return (unsigned)((row * 8 + (c ^ (row & 7))) * 16);
}

// ===========================================================================
// TF32 tensor-core GEMM:  C[m,n] = sum_k A[m,k] * W[n,k]  (+ bias[n])
// Block 128x128x32, 4 warps (2x2), warp tile 64x64 (maximum fragment reuse:
// 4 mma per ldsm). cp.async 3-stage, swizzled smem, 2 CTAs/SM.
// ===========================================================================
#define GBK 32
#define A_TILE_B 16384                 // 128 rows * 8 chunks * 16B
#define STAGE_B  32768                 // A + B
#define NSTAGE   3
#define GEMM_SMEM_BYTES (NSTAGE * STAGE_B)   // 98304

__global__ __launch_bounds__(128, 2) void gemm_tf32(
    const float* __restrict__ A, const float* __restrict__ W,
    const float* __restrict__ bias, float* __restrict__ C,
    int M, int Nc, int K)
{
    extern __shared__ char smc[];
    const unsigned smem_u = (unsigned)__cvta_generic_to_shared(smc);

    const int tid = threadIdx.x;
    const int lane = tid & 31, wid = tid >> 5;
    const int wm = wid & 1, wn = (wid >> 1) & 1;   // 2 x 2 warp grid
    const int m0 = blockIdx.y * 128, n0 = blockIdx.x * 128;

    // staging: thread t loads row t of A and row t of B (8 x 16B chunks each)
    const float* agp = A + (size_t)(m0 + tid) * K;
    const float* bgp = W + (size_t)(n0 + tid) * K;
    unsigned off[8];
#pragma unroll
    for (int c = 0; c < 8; c++) off[c] = swz(tid, c);

#define ISSUE_STAGE(KT) do {                                                 \
    unsigned sb = smem_u + ((KT) % NSTAGE) * STAGE_B;                        \
    const float* ag = agp + (KT) * GBK;                                      \
    const float* bg = bgp + (KT) * GBK;                                      \
    _Pragma("unroll")                                                        \
    for (int c = 0; c < 8; c++) cp16(sb + off[c], ag + c * 4);               \
    _Pragma("unroll")                                                        \
    for (int c = 0; c < 8; c++) cp16(sb + A_TILE_B + off[c], bg + c * 4);    \
} while (0)

    // ldmatrix per-lane row components
    const int t8 = (lane >> 3) & 1;
    const int t16 = lane >> 4;
    const int rr = lane & 7;
    const int rowA = wm * 64 + t8 * 8 + rr;       // + mi*16
    const int rowB = wn * 64 + t16 * 8 + rr;      // + njp*16

    float acc[4][8][4];
#pragma unroll
    for (int i = 0; i < 4; i++)
#pragma unroll
        for (int j = 0; j < 8; j++)
#pragma unroll
            for (int q = 0; q < 4; q++) acc[i][j][q] = 0.f;

    ISSUE_STAGE(0); cp_commit();
    ISSUE_STAGE(1); cp_commit();

    const int nk = K / GBK;
    for (int kt = 0; kt < nk; kt++) {
        cp_wait1();
        __syncthreads();
        if (kt + 2 < nk) { ISSUE_STAGE(kt + 2); }
        cp_commit();

        const unsigned sa = smem_u + (kt % NSTAGE) * STAGE_B;
        const unsigned sbb = sa + A_TILE_B;
#pragma unroll
        for (int ks = 0; ks < 4; ks++) {
            const int ca = 2 * ks + t16;          // A chunk
            const int cb = 2 * ks + t8;           // B chunk
            unsigned af[4][4], bf[4][4];
#pragma unroll
            for (int mi = 0; mi < 4; mi++) {
                int row = rowA + mi * 16;
                ldsm4(af[mi], sa + (unsigned)((row * 8 + (ca ^ (row & 7))) * 16));
            }
#pragma unroll
            for (int njp = 0; njp < 4; njp++) {
                int row = rowB + njp * 16;
                ldsm4(bf[njp], sbb + (unsigned)((row * 8 + (cb ^ (row & 7))) * 16));
            }
#pragma unroll
            for (int mi = 0; mi < 4; mi++)
#pragma unroll
                for (int njp = 0; njp < 4; njp++) {
                    mma_tf32(acc[mi][njp * 2],     af[mi], bf[njp][0], bf[njp][1]);
                    mma_tf32(acc[mi][njp * 2 + 1], af[mi], bf[njp][2], bf[njp][3]);
                }
        }
    }

    // Epilogue: warp owns 64x64 quadrant
#pragma unroll
    for (int mi = 0; mi < 4; mi++) {
        const int r0 = m0 + wm * 64 + mi * 16 + (lane >> 2);
#pragma unroll
        for (int nj = 0; nj < 8; nj++) {
            const int c0 = n0 + wn * 64 + nj * 8 + (lane & 3) * 2;
            float b0 = 0.f, b1 = 0.f;
            if (bias) { b0 = bias[c0]; b1 = bias[c0 + 1]; }
            *(float2*)(C + (size_t)r0 * Nc + c0) =
                make_float2(acc[mi][nj][0] + b0, acc[mi][nj][1] + b1);
            *(float2*)(C + (size_t)(r0 + 8) * Nc + c0) =
                make_float2(acc[mi][nj][2] + b0, acc[mi][nj][3] + b1);
        }
    }
#undef ISSUE_STAGE
}

// ===========================================================================
// Tensor-core attention (unchanged from R7). One CTA per (b,h), 8 warps.
// ===========================================================================
#define AK_ROWS   240
#define AK_FLOATS (AK_ROWS * 96)
#define AV_FLOATS (96 * 256)
#define ATT_SMEM_BYTES ((AK_FLOATS + AV_FLOATS) * 4)   // 190464

__global__ __launch_bounds__(256, 1) void attn_tc_kernel(
    const float* __restrict__ qkv, float* __restrict__ out)
{
    extern __shared__ float smf[];
    float* ks  = smf;                  // [240][96]
    float* vsT = smf + AK_FLOATS;      // [96][256]
    const unsigned ks_u = (unsigned)__cvta_generic_to_shared(ks);
    const unsigned vs_u = (unsigned)__cvta_generic_to_shared(vsT);

    const int bh = blockIdx.x;
    const int b = bh >> 3, h = bh & 7;
    const int tid = threadIdx.x;
    const int w = tid >> 5, lane = tid & 31;
    const float scale = 0.1020620726159658f;
    const size_t base = (size_t)b * NTOK * C3;

    for (int idx = tid; idx < AK_ROWS * 24; idx += 256) {
        const int m = idx / 24, c = idx - m * 24;
        float4 kv = make_float4(0.f, 0.f, 0.f, 0.f);
        if (m < NTOK)
            kv = *(const float4*)(qkv + base + (size_t)m * C3 + CDIM + h * HDIM + c * 4);
        kv.x = f2tf_f(kv.x); kv.y = f2tf_f(kv.y);
        kv.z = f2tf_f(kv.z); kv.w = f2tf_f(kv.w);
        const int cs = (c & 24) | ((c & 7) ^ (m & 7));
        *(float4*)&ks[m * 96 + cs * 4] = kv;
    }
    for (int idx = tid; idx < 24 * AK_ROWS; idx += 256) {
        const int c = idx / AK_ROWS;
        const int m = idx - c * AK_ROWS;
        float4 vv = make_float4(0.f, 0.f, 0.f, 0.f);
        if (m < NTOK)
            vv = *(const float4*)(qkv + base + (size_t)m * C3 + 2 * CDIM + h * HDIM + c * 4);
        const int ch = m >> 2, mi = m & 3;
        float e[4] = {vv.x, vv.y, vv.z, vv.w};
#pragma unroll
        for (int j = 0; j < 4; j++) {
            const int d = c * 4 + j;
            const int chp = (ch & ~7) | ((ch & 7) ^ (d & 7));
            vsT[d * 256 + chp * 4 + mi] = f2tf_f(e[j]);
        }
    }
    __syncthreads();

    const int t8 = (lane >> 3) & 1, t16 = lane >> 4, rr = lane & 7;
    const int lp = lane & 3;
    const int lq = lane >> 2;
    const bool plo = lp < 2;
    const bool kodd = (lp & 1) != 0;
    const int srcl  = (lane & ~3) | (lp >> 1);
    const int srcl2 = (lane & ~3) | ((lp >> 1) + 2);

#pragma unroll 1
    for (int pass = 0; pass < 2; pass++) {
        const int rowbase = pass * 128 + w * 16;
        if (rowbase >= NTOK) continue;

        unsigned qa[12][4];
        {
            const int r0 = rowbase + lq;
            const int r1 = r0 + 8;
            const int rc0 = r0 < NTOK ? r0 : NTOK - 1;
            const int rc1 = r1 < NTOK ? r1 : NTOK - 1;
            const float* q0 = qkv + base + (size_t)rc0 * C3 + h * HDIM;
            const float* q1 = qkv + base + (size_t)rc1 * C3 + h * HDIM;
#pragma unroll
            for (int kf = 0; kf < 12; kf++) {
                const int k0 = kf * 8 + lp;
                qa[kf][0] = f2tf(__float_as_uint(q0[k0] * scale));
                qa[kf][1] = f2tf(__float_as_uint(q1[k0] * scale));
                qa[kf][2] = f2tf(__float_as_uint(q0[k0 + 4] * scale));
                qa[kf][3] = f2tf(__float_as_uint(q1[k0 + 4] * scale));
            }
        }

        float sc[30][4];
#pragma unroll
        for (int nf = 0; nf < 30; nf++)
#pragma unroll
            for (int q = 0; q < 4; q++) sc[nf][q] = 0.f;

#pragma unroll
        for (int g = 0; g < 15; g++) {
            const int row = g * 16 + t16 * 8 + rr;
#pragma unroll
            for (int kf = 0; kf < 12; kf++) {
                const int c = 2 * kf + t8;
                const int cs = (c & 24) | ((c & 7) ^ (row & 7));
                unsigned bf[4];
                ldsm4(bf, ks_u + (unsigned)((row * 96 + cs * 4) * 4));
                mma_tf32(sc[2 * g],     qa[kf], bf[0], bf[1]);
                mma_tf32(sc[2 * g + 1], qa[kf], bf[2], bf[3]);
            }
        }

        float t24[4], t25[4], t26[4];
#pragma unroll
        for (int q = 0; q < 4; q++) {
            t24[q] = __shfl_xor_sync(0xFFFFFFFFu, sc[24][q], 2);
            t25[q] = __shfl_xor_sync(0xFFFFFFFFu, sc[25][q], 2);
            t26[q] = __shfl_xor_sync(0xFFFFFFFFu, sc[26][q], 2);
        }
        const int r1 = rowbase + lq;
        const int r2 = r1 + 8;
#pragma unroll
        for (int half = 0; half < 2; half++) {
            const int row = half ? r2 : r1;
            const int o = half * 2;
            if (row < S1C) {
                sc[27][o]     = plo ? t24[o]     : t25[o];
                sc[27][o + 1] = plo ? t24[o + 1] : t25[o + 1];
                sc[28][o]     = plo ? t25[o]     : t26[o];
                sc[28][o + 1] = plo ? t25[o + 1] : t26[o + 1];
                if (plo) { sc[29][o] = t26[o]; sc[29][o + 1] = t26[o + 1]; }
                if (!plo) { sc[24][o] -= BIASV; sc[24][o + 1] -= BIASV; }
                sc[25][o] -= BIASV; sc[25][o + 1] -= BIASV;
                sc[26][o] -= BIASV; sc[26][o + 1] -= BIASV;
            } else if (row < S2C) {
                sc[27][o] -= BIASV; sc[27][o + 1] -= BIASV;
                sc[28][o] -= BIASV; sc[28][o + 1] -= BIASV;
                if (plo) { sc[29][o] -= BIASV; sc[29][o + 1] -= BIASV; }
            } else {
                if (!plo) { sc[24][o] -= BIASV; sc[24][o + 1] -= BIASV; }
                sc[25][o] -= BIASV; sc[25][o + 1] -= BIASV;
                sc[26][o] -= BIASV; sc[26][o + 1] -= BIASV;
            }
        }
        if (!plo) {
#pragma unroll
            for (int q = 0; q < 4; q++) sc[29][q] = -1e30f;
        }

        float mx1 = -1e30f, mx2 = -1e30f;
#pragma unroll
        for (int nf = 0; nf < 30; nf++) {
            mx1 = fmaxf(mx1, fmaxf(sc[nf][0], sc[nf][1]));
            mx2 = fmaxf(mx2, fmaxf(sc[nf][2], sc[nf][3]));
        }
        mx1 = fmaxf(mx1, __shfl_xor_sync(0xFFFFFFFFu, mx1, 1));
        mx1 = fmaxf(mx1, __shfl_xor_sync(0xFFFFFFFFu, mx1, 2));
        mx2 = fmaxf(mx2, __shfl_xor_sync(0xFFFFFFFFu, mx2, 1));
        mx2 = fmaxf(mx2, __shfl_xor_sync(0xFFFFFFFFu, mx2, 2));

        float sum1 = 0.f, sum2 = 0.f;
#pragma unroll
        for (int nf = 0; nf < 30; nf++) {
            sc[nf][0] = __expf(sc[nf][0] - mx1);
            sc[nf][1] = __expf(sc[nf][1] - mx1);
            sc[nf][2] = __expf(sc[nf][2] - mx2);
            sc[nf][3] = __expf(sc[nf][3] - mx2);
            sum1 += sc[nf][0] + sc[nf][1];
            sum2 += sc[nf][2] + sc[nf][3];
        }
        sum1 += __shfl_xor_sync(0xFFFFFFFFu, sum1, 1);
        sum1 += __shfl_xor_sync(0xFFFFFFFFu, sum1, 2);
        sum2 += __shfl_xor_sync(0xFFFFFFFFu, sum2, 1);
        sum2 += __shfl_xor_sync(0xFFFFFFFFu, sum2, 2);
        const float inv1 = 1.f / sum1;
        const float inv2 = 1.f / sum2;

        float oc[12][4];
#pragma unroll
        for (int nf = 0; nf < 12; nf++)
#pragma unroll
            for (int q = 0; q < 4; q++) oc[nf][q] = 0.f;

#pragma unroll
        for (int kf = 0; kf < 30; kf++) {
            const float v0 = __shfl_sync(0xFFFFFFFFu, sc[kf][0], srcl);
            const float v1 = __shfl_sync(0xFFFFFFFFu, sc[kf][1], srcl);
            const float v2 = __shfl_sync(0xFFFFFFFFu, sc[kf][2], srcl);
            const float v3 = __shfl_sync(0xFFFFFFFFu, sc[kf][3], srcl);
            const float u0 = __shfl_sync(0xFFFFFFFFu, sc[kf][0], srcl2);
            const float u1 = __shfl_sync(0xFFFFFFFFu, sc[kf][1], srcl2);
            const float u2 = __shfl_sync(0xFFFFFFFFu, sc[kf][2], srcl2);
            const float u3 = __shfl_sync(0xFFFFFFFFu, sc[kf][3], srcl2);
            unsigned pa[4];
            pa[0] = f2tf(__float_as_uint(kodd ? v1 : v0));
            pa[1] = f2tf(__float_as_uint(kodd ? v3 : v2));
            pa[2] = f2tf(__float_as_uint(kodd ? u1 : u0));
            pa[3] = f2tf(__float_as_uint(kodd ? u3 : u2));

            const int c = 2 * kf + t8;
#pragma unroll
            for (int dg = 0; dg < 6; dg++) {
                const int d = dg * 16 + t16 * 8 + rr;
                const int cp = (c & ~7) | ((c & 7) ^ (d & 7));
                unsigned bf[4];
                ldsm4(bf, vs_u + (unsigned)((d * 256 + cp * 4) * 4));
                mma_tf32(oc[2 * dg],     pa, bf[0], bf[1]);
                mma_tf32(oc[2 * dg + 1], pa, bf[2], bf[3]);
            }
        }

#pragma unroll
        for (int nf = 0; nf < 12; nf++) {
            const int col = h * HDIM + nf * 8 + 2 * lp;
            if (r1 < NTOK) {
                float2 v = make_float2(f2tf_f(oc[nf][0] * inv1),
                                       f2tf_f(oc[nf][1] * inv1));
                *(float2*)(out + (size_t)(b * NTOK + r1) * CDIM + col) = v;
            }
            if (r2 < NTOK) {
                float2 v = make_float2(f2tf_f(oc[nf][2] * inv2),
                                       f2tf_f(oc[nf][3] * inv2));
                *(float2*)(out + (size_t)(b * NTOK + r2) * CDIM + col) = v;
            }
        }
    }
}

// ===========================================================================
// Launch
// ===========================================================================
extern "C" void kernel_launch(void* const* d_in, const int* in_sizes, int n_in,
                              void* d_out, int out_size)
{
    const float* x      = (const float*)d_in[0];
    const float* qkv_w  = (const float*)d_in[1];
    const float* proj_w = (const float*)d_in[2];
    const float* proj_b = (const float*)d_in[3];
    float* out = (float*)d_out;

    float *qkv_buf, *att_buf, *xc, *wqc, *wpc;
    cudaGetSymbolAddress((void**)&qkv_buf, g_qkv);
    cudaGetSymbolAddress((void**)&att_buf, g_att);
    cudaGetSymbolAddress((void**)&xc,  g_xc);
    cudaGetSymbolAddress((void**)&wqc, g_wqc);
    cudaGetSymbolAddress((void**)&wpc, g_wpc);

    cudaFuncSetAttribute(gemm_tf32,
                         cudaFuncAttributeMaxDynamicSharedMemorySize,
                         GEMM_SMEM_BYTES);
    cudaFuncSetAttribute(attn_tc_kernel,
                         cudaFuncAttributeMaxDynamicSharedMemorySize,
                         ATT_SMEM_BYTES);

    // 0) tf32-round GEMM inputs once
    {
        int n4;
        n4 = (MROWS * CDIM) / 4;
        cvt_tf32_kernel<<<(n4 + 255) / 256, 256>>>(x, xc, n4);
        n4 = (C3 * CDIM) / 4;
        cvt_tf32_kernel<<<(n4 + 255) / 256, 256>>>(qkv_w, wqc, n4);
        n4 = (CDIM * CDIM) / 4;
        cvt_tf32_kernel<<<(n4 + 255) / 256, 256>>>(proj_w, wpc, n4);
    }

    // 1) QKV projection: [15104,768] @ [2304,768]^T -> [15104,2304]
    {
        dim3 grid(C3 / 128, MROWS / 128);   // (18, 118)
        gemm_tf32<<<grid, 128, GEMM_SMEM_BYTES>>>(xc, wqc, nullptr, qkv_buf,
                                                  MROWS, C3, CDIM);
    }

    // 2) Tensor-core attention: 512 CTAs, one per (b,h)
    attn_tc_kernel<<<BATCH * HEADS, 256, ATT_SMEM_BYTES>>>(qkv_buf, att_buf);

    // 3) Output projection: [15104,768] @ [768,768]^T + bias -> [15104,768]
    {
        dim3 grid(CDIM / 128, MROWS / 128); // (6, 118)
        gemm_tf32<<<grid, 128, GEMM_SMEM_BYTES>>>(att_buf, wpc, proj_b, out,
                                                  MROWS, CDIM, CDIM);
    }
}

// round 11
// speedup vs baseline: 1.3004x; 1.3004x over previous
#include <cuda_runtime.h>
#include <cuda_bf16.h>
#include <math.h>
#include <stdint.h>

// Problem constants
#define BATCH   64
#define NTOK    236
#define CDIM    768
#define HEADS   8
#define HDIM    96
#define C3      2304
#define S1C     196
#define S2C     216
#define BIASV   100.0f
#define MROWS   (BATCH * NTOK)   // 15104

// Scratch (device globals; no allocation allowed)
__device__ float g_qkv[(size_t)MROWS * C3];   // [15104, 2304] tf32-rounded
__device__ float g_att[(size_t)MROWS * CDIM]; // [15104, 768]  tf32-rounded
__device__ float g_xc [(size_t)MROWS * CDIM]; // x, tf32-rounded
__device__ float g_wqc[(size_t)C3 * CDIM];    // qkv_w, tf32-rounded
__device__ float g_wpc[(size_t)CDIM * CDIM];  // proj_w, tf32-rounded

__device__ __forceinline__ unsigned f2tf(unsigned x) {
    unsigned y;
    asm volatile("cvt.rna.tf32.f32 %0, %1;\n" : "=r"(y) : "r"(x));
    return y;
}
__device__ __forceinline__ float f2tf_f(float x) {
    return __uint_as_float(f2tf(__float_as_uint(x)));
}

// ---------------------------------------------------------------------------
// Elementwise fp32 -> tf32(rna) pre-conversion (vectorized)
// ---------------------------------------------------------------------------
__global__ __launch_bounds__(256) void cvt_tf32_kernel(
    const float* __restrict__ in, float* __restrict__ out, int n4)
{
    int i = blockIdx.x * blockDim.x + threadIdx.x;
    if (i < n4) {
        float4 v = ((const float4*)in)[i];
        v.x = f2tf_f(v.x); v.y = f2tf_f(v.y);
        v.z = f2tf_f(v.z); v.w = f2tf_f(v.w);
        ((float4*)out)[i] = v;
    }
}

// ---------------------------------------------------------------------------
// MMA / staging helpers
// ---------------------------------------------------------------------------
__device__ __forceinline__ void ldsm4(unsigned* r, unsigned addr) {
    asm volatile("ldmatrix.sync.aligned.m8n8.x4.shared.b16 {%0,%1,%2,%3}, [%4];\n"
        : "=r"(r[0]), "=r"(r[1]), "=r"(r[2]), "=r"(r[3]) : "r"(addr));
}
__device__ __forceinline__ void mma_tf32(float* c, const unsigned* a,
                                         unsigned b0, unsigned b1) {
    asm volatile(
        "mma.sync.aligned.m16n8k8.row.col.f32.tf32.tf32.f32 "
        "{%0,%1,%2,%3}, {%4,%5,%6,%7}, {%8,%9}, {%0,%1,%2,%3};\n"
        : "+f"(c[0]), "+f"(c[1]), "+f"(c[2]), "+f"(c[3])
        : "r"(a[0]), "r"(a[1]), "r"(a[2]), "r"(a[3]), "r"(b0), "r"(b1));
}
__device__ __forceinline__ void cp16(unsigned dst, const void* src) {
    asm volatile("cp.async.cg.shared.global [%0], [%1], 16;\n" :: "r"(dst), "l"(src));
}
__device__ __forceinline__ void cp_commit() {
    asm volatile("cp.async.commit_group;\n" ::);
}
__device__ __forceinline__ void cp_wait1() {
    asm volatile("cp.async.wait_group 1;\n" ::);
}
__device__ __forceinline__ void cp_wait0() {
    asm volatile("cp.async.wait_group 0;\n" ::);
}
__device__ __forceinline__ unsigned swz(int row, int c) {
    return (unsigned)((row * 8 + (c ^ (row & 7))) * 16);
}

// ===========================================================================
// TF32 tensor-core GEMM (R6 config):  C[m,n] = sum_k A[m,k] * W[n,k] (+bias)
// Block 128x128x32, 8 warps (2x4), warp tile 64x32, cp.async 3-stage,
// swizzled smem, 2 CTAs/SM. round_out: tf32-round stores (for QKV output).
// ===========================================================================
#define GBM 128
#define GBN 128
#define GBK 32
#define NSTAGE 3
#define A_TILE_B 16384
#define B_TILE_B 16384
#define STAGE_B  (A_TILE_B + B_TILE_B)
#define GEMM_SMEM_BYTES (NSTAGE * STAGE_B)   // 98304

__global__ __launch_bounds__(256, 2) void gemm_tf32(
    const float* __restrict__ A, const float* __restrict__ W,
    const float* __restrict__ bias, float* __restrict__ C,
    int M, int Nc, int K, int round_out)
{
    extern __shared__ char smc[];
    const unsigned smem_u = (unsigned)__cvta_generic_to_shared(smc);

    const int tid = threadIdx.x;
    const int lane = tid & 31, wid = tid >> 5;
    const int wm = wid & 1, wn = wid >> 1;       // 2 x 4 warp grid
    const int m0 = blockIdx.y * GBM, n0 = blockIdx.x * GBN;

    // staging mapping: 2 threads per row, 16 floats (4 chunks) each
    const int ar = tid >> 1;
    const int ac = (tid & 1) * 4;
    const float* agp = A + (size_t)(m0 + ar) * K + ac * 4;
    const float* bgp = W + (size_t)(n0 + ar) * K + ac * 4;
    unsigned aoff[4], boff[4];
#pragma unroll
    for (int q = 0; q < 4; q++) {
        aoff[q] = swz(ar, ac + q);
        boff[q] = A_TILE_B + swz(ar, ac + q);
    }

#define ISSUE_STAGE(KT) do {                                                 \
    unsigned sb = smem_u + ((KT) % NSTAGE) * STAGE_B;                        \
    const float* ag = agp + (KT) * GBK;                                      \
    const float* bg = bgp + (KT) * GBK;                                      \
    _Pragma("unroll")                                                        \
    for (int q = 0; q < 4; q++) cp16(sb + aoff[q], ag + q * 4);              \
    _Pragma("unroll")                                                        \
    for (int q = 0; q < 4; q++) cp16(sb + boff[q], bg + q * 4);              \
} while (0)

    // ldmatrix per-lane row components
    const int t8 = (lane >> 3) & 1;
    const int t16 = lane >> 4;
    const int rr = lane & 7;
    const int rowA = wm * 64 + t8 * 8 + rr;       // + mi*16
    const int rowB = wn * 32 + t16 * 8 + rr;      // + njp*16

    float acc[4][4][4];
#pragma unroll
    for (int i = 0; i < 4; i++)
#pragma unroll
        for (int j = 0; j < 4; j++)
#pragma unroll
            for (int q = 0; q < 4; q++) acc[i][j][q] = 0.f;

    ISSUE_STAGE(0); cp_commit();
    ISSUE_STAGE(1); cp_commit();

    const int nk = K / GBK;
    for (int kt = 0; kt < nk; kt++) {
        cp_wait1();
        __syncthreads();
        if (kt + 2 < nk) { ISSUE_STAGE(kt + 2); }
        cp_commit();

        const unsigned sa = smem_u + (kt % NSTAGE) * STAGE_B;
        const unsigned sbb = sa + A_TILE_B;
#pragma unroll
        for (int ks = 0; ks < 4; ks++) {
            const int ca = 2 * ks + t16;          // A chunk
            const int cb = 2 * ks + t8;           // B chunk
            unsigned af[4][4], bf[2][4];
#pragma unroll
            for (int mi = 0; mi < 4; mi++) {
                int row = rowA + mi * 16;
                ldsm4(af[mi], sa + (unsigned)((row * 8 + (ca ^ (row & 7))) * 16));
            }
#pragma unroll
            for (int njp = 0; njp < 2; njp++) {
                int row = rowB + njp * 16;
                ldsm4(bf[njp], sbb + (unsigned)((row * 8 + (cb ^ (row & 7))) * 16));
            }
#pragma unroll
            for (int mi = 0; mi < 4; mi++)
#pragma unroll
                for (int njp = 0; njp < 2; njp++) {
                    mma_tf32(acc[mi][njp * 2],     af[mi], bf[njp][0], bf[njp][1]);
                    mma_tf32(acc[mi][njp * 2 + 1], af[mi], bf[njp][2], bf[njp][3]);
                }
        }
    }

    // Epilogue (optionally tf32-rounded stores)
#pragma unroll
    for (int mi = 0; mi < 4; mi++) {
        const int r0 = m0 + wm * 64 + mi * 16 + (lane >> 2);
#pragma unroll
        for (int nj = 0; nj < 4; nj++) {
            const int c0 = n0 + wn * 32 + nj * 8 + (lane & 3) * 2;
            float b0 = 0.f, b1 = 0.f;
            if (bias) { b0 = bias[c0]; b1 = bias[c0 + 1]; }
            float2 v0 = make_float2(acc[mi][nj][0] + b0, acc[mi][nj][1] + b1);
            float2 v1 = make_float2(acc[mi][nj][2] + b0, acc[mi][nj][3] + b1);
            if (round_out) {
                v0.x = f2tf_f(v0.x); v0.y = f2tf_f(v0.y);
                v1.x = f2tf_f(v1.x); v1.y = f2tf_f(v1.y);
            }
            *(float2*)(C + (size_t)r0 * Nc + c0) = v0;
            *(float2*)(C + (size_t)(r0 + 8) * Nc + c0) = v1;
        }
    }
#undef ISSUE_STAGE
}

// ===========================================================================
// Tensor-core attention. qkv is already tf32-rounded, so staging needs no
// conversion: K via cp.async (swizzled), V via LDG/STS transpose.
// ===========================================================================
#define AK_ROWS   240
#define AK_FLOATS (AK_ROWS * 96)
#define AV_FLOATS (96 * 256)
#define ATT_SMEM_BYTES ((AK_FLOATS + AV_FLOATS) * 4)   // 190464

__global__ __launch_bounds__(256, 1) void attn_tc_kernel(
    const float* __restrict__ qkv, float* __restrict__ out)
{
    extern __shared__ float smf[];
    float* ks  = smf;                  // [240][96]
    float* vsT = smf + AK_FLOATS;      // [96][256]
    const unsigned ks_u = (unsigned)__cvta_generic_to_shared(ks);
    const unsigned vs_u = (unsigned)__cvta_generic_to_shared(vsT);

    const int bh = blockIdx.x;
    const int b = bh >> 3, h = bh & 7;
    const int tid = threadIdx.x;
    const int w = tid >> 5, lane = tid & 31;
    const float scale = 0.1020620726159658f;
    const size_t base = (size_t)b * NTOK * C3;

    // ---- K rows 0..235 via cp.async (no cvt needed: qkv pre-rounded) ----
    for (int idx = tid; idx < 236 * 24; idx += 256) {
        const int m = idx / 24, c = idx - m * 24;
        const int cs = (c & 24) | ((c & 7) ^ (m & 7));
        cp16(ks_u + (unsigned)((m * 96 + cs * 4) * 4),
             qkv + base + (size_t)m * C3 + CDIM + h * HDIM + c * 4);
    }
    cp_commit();
    // zero-fill K pad rows 236..239
    if (tid < 96) {
        const int m = 236 + tid / 24;
        const int c = tid % 24;
        const int cs = (c & 24) | ((c & 7) ^ (m & 7));
        *(float4*)&ks[m * 96 + cs * 4] = make_float4(0.f, 0.f, 0.f, 0.f);
    }
    // ---- V^T staging (transpose; overlaps with K cp.async) ----
    for (int idx = tid; idx < 24 * AK_ROWS; idx += 256) {
        const int c = idx / AK_ROWS;
        const int m = idx - c * AK_ROWS;
        float4 vv = make_float4(0.f, 0.f, 0.f, 0.f);
        if (m < NTOK)
            vv = *(const float4*)(qkv + base + (size_t)m * C3 + 2 * CDIM + h * HDIM + c * 4);
        const int ch = m >> 2, mi = m & 3;
        float e[4] = {vv.x, vv.y, vv.z, vv.w};
#pragma unroll
        for (int j = 0; j < 4; j++) {
            const int d = c * 4 + j;
            const int chp = (ch & ~7) | ((ch & 7) ^ (d & 7));
            vsT[d * 256 + chp * 4 + mi] = e[j];
        }
    }
    cp_wait0();
    __syncthreads();

    const int t8 = (lane >> 3) & 1, t16 = lane >> 4, rr = lane & 7;
    const int lp = lane & 3;
    const int lq = lane >> 2;
    const bool plo = lp < 2;
    const bool kodd = (lp & 1) != 0;
    const int srcl  = (lane & ~3) | (lp >> 1);
    const int srcl2 = (lane & ~3) | ((lp >> 1) + 2);

#pragma unroll 1
    for (int pass = 0; pass < 2; pass++) {
        const int rowbase = pass * 128 + w * 16;
        if (rowbase >= NTOK) continue;

        unsigned qa[12][4];
        {
            const int r0 = rowbase + lq;
            const int r1 = r0 + 8;
            const int rc0 = r0 < NTOK ? r0 : NTOK - 1;
            const int rc1 = r1 < NTOK ? r1 : NTOK - 1;
            const float* q0 = qkv + base + (size_t)rc0 * C3 + h * HDIM;
            const float* q1 = qkv + base + (size_t)rc1 * C3 + h * HDIM;
#pragma unroll
            for (int kf = 0; kf < 12; kf++) {
                const int k0 = kf * 8 + lp;
                qa[kf][0] = f2tf(__float_as_uint(q0[k0] * scale));
                qa[kf][1] = f2tf(__float_as_uint(q1[k0] * scale));
                qa[kf][2] = f2tf(__float_as_uint(q0[k0 + 4] * scale));
                qa[kf][3] = f2tf(__float_as_uint(q1[k0 + 4] * scale));
            }
        }

        float sc[30][4];
#pragma unroll
        for (int nf = 0; nf < 30; nf++)
#pragma unroll
            for (int q = 0; q < 4; q++) sc[nf][q] = 0.f;

#pragma unroll
        for (int g = 0; g < 15; g++) {
            const int row = g * 16 + t16 * 8 + rr;
#pragma unroll
            for (int kf = 0; kf < 12; kf++) {
                const int c = 2 * kf + t8;
                const int cs = (c & 24) | ((c & 7) ^ (row & 7));
                unsigned bf[4];
                ldsm4(bf, ks_u + (unsigned)((row * 96 + cs * 4) * 4));
                mma_tf32(sc[2 * g],     qa[kf], bf[0], bf[1]);
                mma_tf32(sc[2 * g + 1], qa[kf], bf[2], bf[3]);
            }
        }

        float t24[4], t25[4], t26[4];
#pragma unroll
        for (int q = 0; q < 4; q++) {
            t24[q] = __shfl_xor_sync(0xFFFFFFFFu, sc[24][q], 2);
            t25[q] = __shfl_xor_sync(0xFFFFFFFFu, sc[25][q], 2);
            t26[q] = __shfl_xor_sync(0xFFFFFFFFu, sc[26][q], 2);
        }
        const int r1 = rowbase + lq;
        const int r2 = r1 + 8;
#pragma unroll
        for (int half = 0; half < 2; half++) {
            const int row = half ? r2 : r1;
            const int o = half * 2;
            if (row < S1C) {
                sc[27][o]     = plo ? t24[o]     : t25[o];
                sc[27][o + 1] = plo ? t24[o + 1] : t25[o + 1];
                sc[28][o]     = plo ? t25[o]     : t26[o];
                sc[28][o + 1] = plo ? t25[o + 1] : t26[o + 1];
                if (plo) { sc[29][o] = t26[o]; sc[29][o + 1] = t26[o + 1]; }
                if (!plo) { sc[24][o] -= BIASV; sc[24][o + 1] -= BIASV; }
                sc[25][o] -= BIASV; sc[25][o + 1] -= BIASV;
                sc[26][o] -= BIASV; sc[26][o + 1] -= BIASV;
            } else if (row < S2C) {
                sc[27][o] -= BIASV; sc[27][o + 1] -= BIASV;
                sc[28][o] -= BIASV; sc[28][o + 1] -= BIASV;
                if (plo) { sc[29][o] -= BIASV; sc[29][o + 1] -= BIASV; }
            } else {
                if (!plo) { sc[24][o] -= BIASV; sc[24][o + 1] -= BIASV; }
                sc[25][o] -= BIASV; sc[25][o + 1] -= BIASV;
                sc[26][o] -= BIASV; sc[26][o + 1] -= BIASV;
            }
        }
        if (!plo) {
#pragma unroll
            for (int q = 0; q < 4; q++) sc[29][q] = -1e30f;
        }

        float mx1 = -1e30f, mx2 = -1e30f;
#pragma unroll
        for (int nf = 0; nf < 30; nf++) {
            mx1 = fmaxf(mx1, fmaxf(sc[nf][0], sc[nf][1]));
            mx2 = fmaxf(mx2, fmaxf(sc[nf][2], sc[nf][3]));
        }
        mx1 = fmaxf(mx1, __shfl_xor_sync(0xFFFFFFFFu, mx1, 1));
        mx1 = fmaxf(mx1, __shfl_xor_sync(0xFFFFFFFFu, mx1, 2));
        mx2 = fmaxf(mx2, __shfl_xor_sync(0xFFFFFFFFu, mx2, 1));
        mx2 = fmaxf(mx2, __shfl_xor_sync(0xFFFFFFFFu, mx2, 2));

        float sum1 = 0.f, sum2 = 0.f;
#pragma unroll
        for (int nf = 0; nf < 30; nf++) {
            sc[nf][0] = __expf(sc[nf][0] - mx1);
            sc[nf][1] = __expf(sc[nf][1] - mx1);
            sc[nf][2] = __expf(sc[nf][2] - mx2);
            sc[nf][3] = __expf(sc[nf][3] - mx2);
            sum1 += sc[nf][0] + sc[nf][1];
            sum2 += sc[nf][2] + sc[nf][3];
        }
        sum1 += __shfl_xor_sync(0xFFFFFFFFu, sum1, 1);
        sum1 += __shfl_xor_sync(0xFFFFFFFFu, sum1, 2);
        sum2 += __shfl_xor_sync(0xFFFFFFFFu, sum2, 1);
        sum2 += __shfl_xor_sync(0xFFFFFFFFu, sum2, 2);
        const float inv1 = 1.f / sum1;
        const float inv2 = 1.f / sum2;

        float oc[12][4];
#pragma unroll
        for (int nf = 0; nf < 12; nf++)
#pragma unroll
            for (int q = 0; q < 4; q++) oc[nf][q] = 0.f;

#pragma unroll
        for (int kf = 0; kf < 30; kf++) {
            const float v0 = __shfl_sync(0xFFFFFFFFu, sc[kf][0], srcl);
            const float v1 = __shfl_sync(0xFFFFFFFFu, sc[kf][1], srcl);
            const float v2 = __shfl_sync(0xFFFFFFFFu, sc[kf][2], srcl);
            const float v3 = __shfl_sync(0xFFFFFFFFu, sc[kf][3], srcl);
            const float u0 = __shfl_sync(0xFFFFFFFFu, sc[kf][0], srcl2);
            const float u1 = __shfl_sync(0xFFFFFFFFu, sc[kf][1], srcl2);
            const float u2 = __shfl_sync(0xFFFFFFFFu, sc[kf][2], srcl2);
            const float u3 = __shfl_sync(0xFFFFFFFFu, sc[kf][3], srcl2);
            unsigned pa[4];
            pa[0] = f2tf(__float_as_uint(kodd ? v1 : v0));
            pa[1] = f2tf(__float_as_uint(kodd ? v3 : v2));
            pa[2] = f2tf(__float_as_uint(kodd ? u1 : u0));
            pa[3] = f2tf(__float_as_uint(kodd ? u3 : u2));

            const int c = 2 * kf + t8;
#pragma unroll
            for (int dg = 0; dg < 6; dg++) {
                const int d = dg * 16 + t16 * 8 + rr;
                const int cp = (c & ~7) | ((c & 7) ^ (d & 7));
                unsigned bf[4];
                ldsm4(bf, vs_u + (unsigned)((d * 256 + cp * 4) * 4));
                mma_tf32(oc[2 * dg],     pa, bf[0], bf[1]);
                mma_tf32(oc[2 * dg + 1], pa, bf[2], bf[3]);
            }
        }

#pragma unroll
        for (int nf = 0; nf < 12; nf++) {
            const int col = h * HDIM + nf * 8 + 2 * lp;
            if (r1 < NTOK) {
                float2 v = make_float2(f2tf_f(oc[nf][0] * inv1),
                                       f2tf_f(oc[nf][1] * inv1));
                *(float2*)(out + (size_t)(b * NTOK + r1) * CDIM + col) = v;
            }
            if (r2 < NTOK) {
                float2 v = make_float2(f2tf_f(oc[nf][2] * inv2),
                                       f2tf_f(oc[nf][3] * inv2));
                *(float2*)(out + (size_t)(b * NTOK + r2) * CDIM + col) = v;
            }
        }
    }
}

// ===========================================================================
// Launch
// ===========================================================================
extern "C" void kernel_launch(void* const* d_in, const int* in_sizes, int n_in,
                              void* d_out, int out_size)
{
    const float* x      = (const float*)d_in[0];
    const float* qkv_w  = (const float*)d_in[1];
    const float* proj_w = (const float*)d_in[2];
    const float* proj_b = (const float*)d_in[3];
    float* out = (float*)d_out;

    float *qkv_buf, *att_buf, *xc, *wqc, *wpc;
    cudaGetSymbolAddress((void**)&qkv_buf, g_qkv);
    cudaGetSymbolAddress((void**)&att_buf, g_att);
    cudaGetSymbolAddress((void**)&xc,  g_xc);
    cudaGetSymbolAddress((void**)&wqc, g_wqc);
    cudaGetSymbolAddress((void**)&wpc, g_wpc);

    cudaFuncSetAttribute(gemm_tf32,
                         cudaFuncAttributeMaxDynamicSharedMemorySize,
                         GEMM_SMEM_BYTES);
    cudaFuncSetAttribute(attn_tc_kernel,
                         cudaFuncAttributeMaxDynamicSharedMemorySize,
                         ATT_SMEM_BYTES);

    // 0) tf32-round GEMM inputs once
    {
        int n4;
        n4 = (MROWS * CDIM) / 4;
        cvt_tf32_kernel<<<(n4 + 255) / 256, 256>>>(x, xc, n4);
        n4 = (C3 * CDIM) / 4;
        cvt_tf32_kernel<<<(n4 + 255) / 256, 256>>>(qkv_w, wqc, n4);
        n4 = (CDIM * CDIM) / 4;
        cvt_tf32_kernel<<<(n4 + 255) / 256, 256>>>(proj_w, wpc, n4);
    }

    // 1) QKV projection (tf32-rounded output feeds attention directly)
    {
        dim3 grid(C3 / GBN, MROWS / GBM);   // (18, 118)
        gemm_tf32<<<grid, 256, GEMM_SMEM_BYTES>>>(xc, wqc, nullptr, qkv_buf,
                                                  MROWS, C3, CDIM, 1);
    }

    // 2) Tensor-core attention: 512 CTAs, one per (b,h)
    attn_tc_kernel<<<BATCH * HEADS, 256, ATT_SMEM_BYTES>>>(qkv_buf, att_buf);

    // 3) Output projection: [15104,768] @ [768,768]^T + bias -> [15104,768]
    {
        dim3 grid(CDIM / GBN, MROWS / GBM); // (6, 118)
        gemm_tf32<<<grid, 256, GEMM_SMEM_BYTES>>>(att_buf, wpc, proj_b, out,
                                                  MROWS, CDIM, CDIM, 0);
    }
}